// round 2
// baseline (speedup 1.0000x reference)
#include <cuda_runtime.h>
#include <cuda_bf16.h>
#include <cstdint>

// Problem constants (fixed shapes from reference setup_inputs)
#define B_   8
#define S_   4096
#define H_   768      // K of GEMM
#define D_   1024     // N of GEMM
#define W_   2048     // MAX_WORDS
#define M_   (B_ * W_)   // 16384 rows of GEMM

// 50.3 MB scratch for pooled (masked-mean) token embeddings, row-major [M_, H_]
__device__ float g_token_emb[(size_t)M_ * H_];

// ---------------------------------------------------------------------------
// Kernel 1: per-(b,w) segment masked-mean pooling.
// word_ids sorted per batch -> each word's subwords are a contiguous run.
// One CTA per (batch, word). Binary search run bounds, reduce, write mean.
// Also writes the token mask (as float) into the tail of d_out.
// Writes directly to the __device__ global scratch (no symbol lookup needed).
// ---------------------------------------------------------------------------
__global__ void __launch_bounds__(256)
seg_mean_kernel(const float* __restrict__ emb,      // [B,S,H]
                const int*   __restrict__ masks,    // [B,S]
                const int*   __restrict__ wids,     // [B,S] sorted per b
                float*       __restrict__ mask_out) // [M_] (float 0/1)
{
    const int w = blockIdx.x;   // word id  [0, W_)
    const int b = blockIdx.y;   // batch    [0, B_)
    const int* row = wids + (size_t)b * S_;

    // lower bound: first s with row[s] >= w
    int lo = 0, hi = S_;
    while (lo < hi) { int m = (lo + hi) >> 1; if (row[m] < w) lo = m + 1; else hi = m; }
    const int start = lo;
    // upper bound: first s with row[s] > w
    hi = S_;
    while (lo < hi) { int m = (lo + hi) >> 1; if (row[m] <= w) lo = m + 1; else hi = m; }
    const int end = lo;
    const int count = end - start;

    __shared__ int s_ok;
    if (threadIdx.x == 0) s_ok = 1;
    __syncthreads();
    const int* mrow = masks + (size_t)b * S_;
    for (int s = start + threadIdx.x; s < end; s += blockDim.x)
        if (mrow[s] == 0) s_ok = 0;   // benign race: all writers write 0
    __syncthreads();

    const bool valid = (count > 0) && (s_ok != 0);
    const float inv = valid ? (1.0f / (float)count) : 0.0f;

    const float* ebase = emb + (size_t)b * S_ * H_;
    float* trow = g_token_emb + ((size_t)b * W_ + w) * H_;

    for (int h = threadIdx.x; h < H_; h += blockDim.x) {
        float acc = 0.0f;
        for (int s = start; s < end; ++s)
            acc += ebase[(size_t)s * H_ + h];
        trow[h] = acc * inv;            // 0 if invalid
    }
    if (threadIdx.x == 0)
        mask_out[(size_t)b * W_ + w] = valid ? 1.0f : 0.0f;
}

// ---------------------------------------------------------------------------
// Kernel 2: SGEMM  C[M,N] = A[M,K] * B[K,N] + bias[N]
// Classic 128x128x8 tiling, 256 threads, 8x8 microtile, float4 ld/st.
// M=16384, N=1024, K=768 (all divisible by tile dims -> no bounds checks).
// A is the __device__ global scratch g_token_emb.
// ---------------------------------------------------------------------------
#define BM 128
#define BN 128
#define BK 8
#define TM 8
#define TN 8

__global__ void __launch_bounds__(256)
sgemm_bias_kernel(const float* __restrict__ Bmat,  // [H_,D_]
                  const float* __restrict__ bias,  // [D_]
                  float*       __restrict__ C)     // [M_,D_]
{
    __shared__ float As[BK][BM];
    __shared__ float Bs[BK][BN];

    const int tid = threadIdx.x;
    const int bx = blockIdx.x;   // over N
    const int by = blockIdx.y;   // over M

    const float* Ab = g_token_emb + (size_t)by * BM * H_;
    const float* Bb = Bmat + (size_t)bx * BN;

    // A tile: 128 rows x 8 cols = 256 float4. thread -> (row, 4-col chunk)
    const int arow = tid >> 1;
    const int acol = (tid & 1) * 4;
    // B tile: 8 rows x 128 cols = 256 float4. thread -> (row, 4-col chunk)
    const int brow = tid >> 5;
    const int bcol = (tid & 31) * 4;

    const int tx = tid & 15;     // 16 threads over N
    const int ty = tid >> 4;     // 16 threads over M

    float acc[TM][TN];
    #pragma unroll
    for (int i = 0; i < TM; ++i)
        #pragma unroll
        for (int j = 0; j < TN; ++j) acc[i][j] = 0.0f;

    for (int k0 = 0; k0 < H_; k0 += BK) {
        const float4 av = *(const float4*)(Ab + (size_t)arow * H_ + k0 + acol);
        const float4 bv = *(const float4*)(Bb + (size_t)(k0 + brow) * D_ + bcol);
        __syncthreads();   // previous compute done before smem overwrite
        As[acol + 0][arow] = av.x;
        As[acol + 1][arow] = av.y;
        As[acol + 2][arow] = av.z;
        As[acol + 3][arow] = av.w;
        *(float4*)&Bs[brow][bcol] = bv;
        __syncthreads();

        #pragma unroll
        for (int kk = 0; kk < BK; ++kk) {
            float af[TM], bf[TN];
            const float4 a0 = *(const float4*)&As[kk][ty * TM];
            const float4 a1 = *(const float4*)&As[kk][ty * TM + 4];
            const float4 b0 = *(const float4*)&Bs[kk][tx * TN];
            const float4 b1 = *(const float4*)&Bs[kk][tx * TN + 4];
            af[0]=a0.x; af[1]=a0.y; af[2]=a0.z; af[3]=a0.w;
            af[4]=a1.x; af[5]=a1.y; af[6]=a1.z; af[7]=a1.w;
            bf[0]=b0.x; bf[1]=b0.y; bf[2]=b0.z; bf[3]=b0.w;
            bf[4]=b1.x; bf[5]=b1.y; bf[6]=b1.z; bf[7]=b1.w;
            #pragma unroll
            for (int i = 0; i < TM; ++i)
                #pragma unroll
                for (int j = 0; j < TN; ++j)
                    acc[i][j] = fmaf(af[i], bf[j], acc[i][j]);
        }
    }

    // epilogue: add bias, store two float4 per row of the microtile
    const int crow0 = by * BM + ty * TM;
    const int ccol0 = bx * BN + tx * TN;
    float4 bias0 = *(const float4*)(bias + ccol0);
    float4 bias1 = *(const float4*)(bias + ccol0 + 4);
    #pragma unroll
    for (int i = 0; i < TM; ++i) {
        float4 o0, o1;
        o0.x = acc[i][0] + bias0.x; o0.y = acc[i][1] + bias0.y;
        o0.z = acc[i][2] + bias0.z; o0.w = acc[i][3] + bias0.w;
        o1.x = acc[i][4] + bias1.x; o1.y = acc[i][5] + bias1.y;
        o1.z = acc[i][6] + bias1.z; o1.w = acc[i][7] + bias1.w;
        float* crow = C + (size_t)(crow0 + i) * D_ + ccol0;
        *(float4*)crow       = o0;
        *(float4*)(crow + 4) = o1;
    }
}

// ---------------------------------------------------------------------------
// Launch: inputs in metadata order:
//   d_in[0] embeddings f32 [B,S,H]
//   d_in[1] proj_w     f32 [H,D]
//   d_in[2] proj_b     f32 [D]
//   d_in[3] masks      i32 [B,S]
//   d_in[4] word_ids   i32 [B,S]
// d_out: [ out (B*W*D f32) | token_masks (B*W, as f32 0/1) ]
// ---------------------------------------------------------------------------
extern "C" void kernel_launch(void* const* d_in, const int* in_sizes, int n_in,
                              void* d_out, int out_size)
{
    const float* emb    = (const float*)d_in[0];
    const float* proj_w = (const float*)d_in[1];
    const float* proj_b = (const float*)d_in[2];
    const int*   masks  = (const int*)d_in[3];
    const int*   wids   = (const int*)d_in[4];

    float* out_proj  = (float*)d_out;                       // [M_, D_]
    float* out_masks = (float*)d_out + (size_t)M_ * D_;     // [M_]

    dim3 g1(W_, B_);
    seg_mean_kernel<<<g1, 256>>>(emb, masks, wids, out_masks);

    dim3 g2(D_ / BN, M_ / BM);   // (8, 128)
    sgemm_bias_kernel<<<g2, 256>>>(proj_w, proj_b, out_proj);
}

// round 7
// speedup vs baseline: 2.2011x; 2.2011x over previous
#include <cuda_runtime.h>
#include <cuda_bf16.h>
#include <cstdint>

// Problem constants (fixed shapes)
#define B_   8
#define S_   4096
#define H_   768      // K of GEMM
#define D_   1024     // N of GEMM
#define W_   2048     // MAX_WORDS
#define M_   (B_ * W_)   // 16384 GEMM rows

// ---------------------------------------------------------------------------
// Device scratch (no allocations allowed anywhere)
// ---------------------------------------------------------------------------
__device__ __nv_bfloat16 g_a_hi[(size_t)M_ * H_];   // pooled rows, hi plane
__device__ __nv_bfloat16 g_a_lo[(size_t)M_ * H_];   // pooled rows, lo plane
__device__ __nv_bfloat16 g_bt_hi[(size_t)D_ * H_];  // proj_w^T [N][K] hi
__device__ __nv_bfloat16 g_bt_lo[(size_t)D_ * H_];  // proj_w^T [N][K] lo

// ---------------------------------------------------------------------------
// Kernel 1: per-(b,w) segment masked-mean pooling (R2-validated binary search).
// Writes bf16 hi/lo split planes + float mask into tail of d_out.
// ---------------------------------------------------------------------------
__global__ void __launch_bounds__(256)
seg_mean_kernel(const float* __restrict__ emb,      // [B,S,H]
                const int*   __restrict__ masks,    // [B,S]
                const int*   __restrict__ wids,     // [B,S] sorted per b
                float*       __restrict__ mask_out) // [M_]
{
    const int w = blockIdx.x;   // word id  [0, W_)
    const int b = blockIdx.y;   // batch    [0, B_)
    const int* row = wids + (size_t)b * S_;

    // lower bound: first s with row[s] >= w
    int lo = 0, hi = S_;
    while (lo < hi) { int m = (lo + hi) >> 1; if (row[m] < w) lo = m + 1; else hi = m; }
    const int start = lo;
    // upper bound: first s with row[s] > w
    hi = S_;
    while (lo < hi) { int m = (lo + hi) >> 1; if (row[m] <= w) lo = m + 1; else hi = m; }
    const int end = lo;
    const int count = end - start;

    __shared__ int s_ok;
    if (threadIdx.x == 0) s_ok = 1;
    __syncthreads();
    const int* mrow = masks + (size_t)b * S_;
    for (int s = start + threadIdx.x; s < end; s += 256)
        if (mrow[s] == 0) s_ok = 0;   // benign race: all writers write 0
    __syncthreads();

    const bool valid = (count > 0) && (s_ok != 0);
    const float inv = valid ? (1.0f / (float)count) : 0.0f;

    const float* ebase = emb + (size_t)b * S_ * H_;
    const int idx = b * W_ + w;
    __nv_bfloat16* ohi = g_a_hi + (size_t)idx * H_;
    __nv_bfloat16* olo = g_a_lo + (size_t)idx * H_;

    for (int h = threadIdx.x; h < H_; h += 256) {
        float acc = 0.0f;
        for (int s = start; s < end; ++s)
            acc += ebase[(size_t)s * H_ + h];
        float v = acc * inv;            // 0 if invalid
        __nv_bfloat16 vh = __float2bfloat16(v);
        ohi[h] = vh;
        olo[h] = __float2bfloat16(v - __bfloat162float(vh));
    }
    if (threadIdx.x == 0)
        mask_out[idx] = valid ? 1.0f : 0.0f;
}

// ---------------------------------------------------------------------------
// Kernel 2: proj_w [K=768][N=1024] -> transposed bf16 hi/lo planes [N][K]
// ---------------------------------------------------------------------------
__global__ void __launch_bounds__(256)
wsplit_kernel(const float* __restrict__ w)
{
    __shared__ float t[32][33];
    const int nx = blockIdx.x * 32, kx = blockIdx.y * 32;
    const int tx = threadIdx.x, ty = threadIdx.y;   // 32 x 8
    #pragma unroll
    for (int j = 0; j < 32; j += 8)
        t[ty + j][tx] = w[(size_t)(kx + ty + j) * D_ + nx + tx];
    __syncthreads();
    #pragma unroll
    for (int j = 0; j < 32; j += 8) {
        int n = nx + ty + j, k = kx + tx;
        float v = t[tx][ty + j];
        __nv_bfloat16 vh = __float2bfloat16(v);
        g_bt_hi[(size_t)n * H_ + k] = vh;
        g_bt_lo[(size_t)n * H_ + k] = __float2bfloat16(v - __bfloat162float(vh));
    }
}

// ---------------------------------------------------------------------------
// mma.sync / ldmatrix helpers (sm_80+ -- legal on BOTH device compile passes)
// ---------------------------------------------------------------------------
__device__ __forceinline__ void ldsm_x4(uint32_t* r, uint32_t addr) {
    asm volatile("ldmatrix.sync.aligned.m8n8.x4.shared.b16 {%0,%1,%2,%3}, [%4];"
                 : "=r"(r[0]), "=r"(r[1]), "=r"(r[2]), "=r"(r[3]) : "r"(addr));
}
__device__ __forceinline__ void mma_bf16(float* d, const uint32_t* a, const uint32_t* b) {
    asm volatile(
        "mma.sync.aligned.m16n8k16.row.col.f32.bf16.bf16.f32 "
        "{%0,%1,%2,%3}, {%4,%5,%6,%7}, {%8,%9}, {%0,%1,%2,%3};"
        : "+f"(d[0]), "+f"(d[1]), "+f"(d[2]), "+f"(d[3])
        : "r"(a[0]), "r"(a[1]), "r"(a[2]), "r"(a[3]), "r"(b[0]), "r"(b[1]));
}

// ---------------------------------------------------------------------------
// Kernel 3: GEMM via mma.sync bf16, 3-product split, fp32 accum.
//   C[M,N] = Ahi*Bhi + Ahi*Blo + Alo*Bhi + bias
// Block tile 128x128, BK=32; 8 warps, warp tile 64x32 (4 m16 x 4 n8 frags).
// smem pitch 40 bf16 (80B) -> ldmatrix conflict-free (banks r*20 mod 32).
// ---------------------------------------------------------------------------
#define BK 32
#define PITCH 40   // bf16 elements per smem row

__global__ void __launch_bounds__(256, 2)
gemm_mma_kernel(const float* __restrict__ bias, float* __restrict__ C)
{
    __shared__ __align__(16) __nv_bfloat16 sAh[128 * PITCH];
    __shared__ __align__(16) __nv_bfloat16 sAl[128 * PITCH];
    __shared__ __align__(16) __nv_bfloat16 sBh[128 * PITCH];
    __shared__ __align__(16) __nv_bfloat16 sBl[128 * PITCH];

    const int tid  = threadIdx.x;
    const int wid  = tid >> 5;
    const int lane = tid & 31;
    const int m0 = blockIdx.y * 128;
    const int n0 = blockIdx.x * 128;
    const int wm = (wid & 1) * 64;     // warp M origin within tile
    const int wn = (wid >> 1) * 32;    // warp N origin within tile

    const uint32_t sAh_b = (uint32_t)__cvta_generic_to_shared(sAh);
    const uint32_t sAl_b = (uint32_t)__cvta_generic_to_shared(sAl);
    const uint32_t sBh_b = (uint32_t)__cvta_generic_to_shared(sBh);
    const uint32_t sBl_b = (uint32_t)__cvta_generic_to_shared(sBl);

    // Per-lane ldmatrix source coordinates (within a 16x16 block at (r0, ko)):
    // A mapping: mat = lane>>3;  row += (mat&1)*8;  col += (mat>>1)*8
    // B mapping: mat = lane>>3;  row += (mat>>1)*8; col += (mat&1)*8
    const int matq = lane >> 3;
    const int lrow = lane & 7;
    const int a_r = lrow + ((matq & 1) << 3);
    const int a_c = (matq >> 1) << 3;
    const int b_r = lrow + ((matq >> 1) << 3);
    const int b_c = (matq & 1) << 3;

    float acc[4][4][4];
    #pragma unroll
    for (int i = 0; i < 4; ++i)
        #pragma unroll
        for (int j = 0; j < 4; ++j)
            #pragma unroll
            for (int k = 0; k < 4; ++k) acc[i][j][k] = 0.0f;

    for (int k0 = 0; k0 < H_; k0 += BK) {
        __syncthreads();   // previous iteration's math done before overwrite
        // Fill tiles: 128 rows x 32 bf16 (64B = 4 uint4) per plane.
        #pragma unroll
        for (int i = tid; i < 512; i += 256) {
            const int r = i >> 2;
            const int c = (i & 3) << 3;     // bf16 col, 8 per uint4
            const size_t ga = (size_t)(m0 + r) * H_ + k0 + c;
            const size_t gb = (size_t)(n0 + r) * H_ + k0 + c;
            *(uint4*)&sAh[r * PITCH + c] = *(const uint4*)&g_a_hi[ga];
            *(uint4*)&sAl[r * PITCH + c] = *(const uint4*)&g_a_lo[ga];
            *(uint4*)&sBh[r * PITCH + c] = *(const uint4*)&g_bt_hi[gb];
            *(uint4*)&sBl[r * PITCH + c] = *(const uint4*)&g_bt_lo[gb];
        }
        __syncthreads();

        #pragma unroll
        for (int ks = 0; ks < 2; ++ks) {
            const int ko = ks * 16;
            uint32_t ah[4][4], bh[4][2], bl[4][2];
            // A hi fragments (4 x m16)
            #pragma unroll
            for (int mf = 0; mf < 4; ++mf) {
                const int r = wm + mf * 16 + a_r;
                ldsm_x4(ah[mf], sAh_b + (uint32_t)(r * PITCH + ko + a_c) * 2);
            }
            // B hi / lo fragments (2 x n16 -> 4 x n8)
            #pragma unroll
            for (int np = 0; np < 2; ++np) {
                const int r = wn + np * 16 + b_r;
                const uint32_t off = (uint32_t)(r * PITCH + ko + b_c) * 2;
                uint32_t q[4];
                ldsm_x4(q, sBh_b + off);
                bh[np * 2][0] = q[0]; bh[np * 2][1] = q[1];
                bh[np * 2 + 1][0] = q[2]; bh[np * 2 + 1][1] = q[3];
                ldsm_x4(q, sBl_b + off);
                bl[np * 2][0] = q[0]; bl[np * 2][1] = q[1];
                bl[np * 2 + 1][0] = q[2]; bl[np * 2 + 1][1] = q[3];
            }
            // products: Ahi*Bhi + Ahi*Blo
            #pragma unroll
            for (int mf = 0; mf < 4; ++mf)
                #pragma unroll
                for (int nf = 0; nf < 4; ++nf) {
                    mma_bf16(acc[mf][nf], ah[mf], bh[nf]);
                    mma_bf16(acc[mf][nf], ah[mf], bl[nf]);
                }
            // A lo fragments (reuse pressure window: Blo now dead)
            uint32_t al[4][4];
            #pragma unroll
            for (int mf = 0; mf < 4; ++mf) {
                const int r = wm + mf * 16 + a_r;
                ldsm_x4(al[mf], sAl_b + (uint32_t)(r * PITCH + ko + a_c) * 2);
            }
            // product: Alo*Bhi
            #pragma unroll
            for (int mf = 0; mf < 4; ++mf)
                #pragma unroll
                for (int nf = 0; nf < 4; ++nf)
                    mma_bf16(acc[mf][nf], al[mf], bh[nf]);
        }
    }

    // Epilogue: direct gmem stores with bias. C frag: lane l -> rows l/4, l/4+8;
    // cols (l%4)*2, +1 within each m16n8 subtile.
    const int cr = lane >> 2;
    const int cc = (lane & 3) * 2;
    #pragma unroll
    for (int mf = 0; mf < 4; ++mf) {
        #pragma unroll
        for (int nf = 0; nf < 4; ++nf) {
            const int gr0 = m0 + wm + mf * 16 + cr;
            const int gc  = n0 + wn + nf * 8 + cc;
            const float b0 = bias[gc], b1 = bias[gc + 1];
            float2 v0 = make_float2(acc[mf][nf][0] + b0, acc[mf][nf][1] + b1);
            float2 v1 = make_float2(acc[mf][nf][2] + b0, acc[mf][nf][3] + b1);
            *(float2*)&C[(size_t)gr0 * D_ + gc]       = v0;
            *(float2*)&C[(size_t)(gr0 + 8) * D_ + gc] = v1;
        }
    }
}

// ---------------------------------------------------------------------------
// Launch. Inputs (metadata order):
//   d_in[0] embeddings f32 [B,S,H]; d_in[1] proj_w f32 [H,D]; d_in[2] proj_b f32 [D]
//   d_in[3] masks i32 [B,S]; d_in[4] word_ids i32 [B,S]
// d_out: [ out (M_*D_ f32) | token_masks (M_ f32 0/1) ]
// ---------------------------------------------------------------------------
extern "C" void kernel_launch(void* const* d_in, const int* in_sizes, int n_in,
                              void* d_out, int out_size)
{
    const float* emb    = (const float*)d_in[0];
    const float* proj_w = (const float*)d_in[1];
    const float* proj_b = (const float*)d_in[2];
    const int*   masks  = (const int*)d_in[3];
    const int*   wids   = (const int*)d_in[4];

    float* out_proj  = (float*)d_out;
    float* out_masks = (float*)d_out + (size_t)M_ * D_;

    dim3 g1(W_, B_);
    seg_mean_kernel<<<g1, 256>>>(emb, masks, wids, out_masks);

    dim3 gw(D_ / 32, H_ / 32);
    wsplit_kernel<<<gw, dim3(32, 8)>>>(proj_w);

    dim3 g2(D_ / 128, M_ / 128);   // (8, 128)
    gemm_mma_kernel<<<g2, 256>>>(proj_b, out_proj);
}